// round 4
// baseline (speedup 1.0000x reference)
#include <cuda_runtime.h>

// Problem constants
#define Vv 50000
#define Ee 128
#define Hh 64
#define Gg 256   // 4*H
#define Bb 512
#define Ss 512

// 51.2 MB scratch: projTable[v][g] = emb[v] @ Wih0^T + (bih0+bhh0)
__device__ float g_projT[Vv * (size_t)Gg];
__device__ int g_is64;

typedef unsigned long long ull;

__device__ __forceinline__ ull ffma2(ull a, ull b, ull acc) {
    ull d;
    asm("fma.rn.f32x2 %0, %1, %2, %3;" : "=l"(d) : "l"(a), "l"(b), "l"(acc));
    return d;
}
__device__ __forceinline__ ull pack2(float lo, float hi) {
    return ((ull)__float_as_uint(hi) << 32) | (ull)__float_as_uint(lo);
}
__device__ __forceinline__ float hsum2(ull a) {
    return __uint_as_float((unsigned int)a) + __uint_as_float((unsigned int)(a >> 32));
}
__device__ __forceinline__ float sigmf(float x) {
    return 1.0f / (1.0f + __expf(-x));
}

// ---------------------------------------------------------------------------
// Detect whether input_seq is int64 or int32 (jax silently downcasts without
// x64). int64 little-endian values < 2^31 have all-zero high words.
// ---------------------------------------------------------------------------
__global__ void detect_kernel(const unsigned int* __restrict__ w) {
    if (threadIdx.x == 0) {
        int is64 = 1;
        for (int i = 0; i < 128; ++i)
            if (w[2 * i + 1] != 0u) { is64 = 0; break; }
        g_is64 = is64;
    }
}

// ---------------------------------------------------------------------------
// Phase A: projTable[V,256] = emb[V,128] @ Wih0^T[128,256] + (bih0+bhh0)
// 32 v-rows per CTA; Wih0 (128KB) + emb tile in smem as packed f32x2.
// ---------------------------------------------------------------------------
__global__ void __launch_bounds__(256, 1)
proj_kernel(const float* __restrict__ emb, const float* __restrict__ Wih0,
            const float* __restrict__ bih0, const float* __restrict__ bhh0) {
    extern __shared__ ull sm[];
    ull* Wsm = sm;               // [64 k2][256 g]
    ull* Esm = sm + 64 * 256;    // [64 k2][32 r]

    const int tid = threadIdx.x;
    const int v0 = blockIdx.x * 32;

    // Load Wih0: global [g][e] row-major -> smem [k2][g] as (e=2k2, 2k2+1) pair
    for (int i = tid; i < 256 * 64; i += 256) {
        int gg = i >> 6, k2 = i & 63;
        float2 w = *reinterpret_cast<const float2*>(Wih0 + (size_t)gg * Ee + 2 * k2);
        Wsm[k2 * 256 + gg] = pack2(w.x, w.y);
    }
    // Load 32 emb rows -> smem [k2][r]
    for (int i = tid; i < 32 * 64; i += 256) {
        int r = i >> 6, k2 = i & 63;
        int v = v0 + r;
        float2 e = make_float2(0.f, 0.f);
        if (v < Vv) e = *reinterpret_cast<const float2*>(emb + (size_t)v * Ee + 2 * k2);
        Esm[k2 * 32 + r] = pack2(e.x, e.y);
    }
    __syncthreads();

    const int gg = tid;  // output column
    ull acc[32];
#pragma unroll
    for (int r = 0; r < 32; ++r) acc[r] = 0ull;

#pragma unroll 2
    for (int k2 = 0; k2 < 64; ++k2) {
        ull w = Wsm[k2 * 256 + gg];
        const ull* ep = &Esm[k2 * 32];
#pragma unroll
        for (int r = 0; r < 32; ++r) acc[r] = ffma2(ep[r], w, acc[r]);
    }

    float b0 = bih0[gg] + bhh0[gg];
#pragma unroll
    for (int r = 0; r < 32; ++r) {
        int v = v0 + r;
        if (v < Vv) g_projT[(size_t)v * Gg + gg] = hsum2(acc[r]) + b0;
    }
}

// ---------------------------------------------------------------------------
// Phase B: fused 2-layer LSTM recurrence + final FC.
// 128 CTAs x 4 batch rows; Whh0/Wih1/Whh1 (192KB) in smem packed f32x2,
// h0/h1/c0/c1 on-chip for the whole sequence. No y0/xproj materialization.
// ---------------------------------------------------------------------------
__global__ void __launch_bounds__(256, 1)
lstm_kernel(const void* __restrict__ seq_raw,
            const float* __restrict__ Whh0g, const float* __restrict__ Wih1g,
            const float* __restrict__ Whh1g,
            const float* __restrict__ bih1, const float* __restrict__ bhh1,
            const float* __restrict__ Wfc, const float* __restrict__ bfc,
            float* __restrict__ out) {
    extern __shared__ ull sm[];
    ull* W0 = sm;                 // Whh0 [32 k2][256 g]
    ull* Wa = sm + 32 * 256;      // Wih1
    ull* Wb = sm + 2 * 32 * 256;  // Whh1
    float* fbase = (float*)(sm + 3 * 32 * 256);
    float* h0s = fbase;                  // [4][64]
    float* h1s = fbase + 256;            // [4][64]
    float* gts = fbase + 512;            // [256][5] padded gate exchange
    float* b1s = fbase + 512 + 1280;     // [256]
    int*   idxs = (int*)(fbase + 512 + 1280 + 256);  // [4][512]

    const int tid = threadIdx.x;
    const int brow0 = blockIdx.x * 4;

    // Load the three recurrent weight matrices ([256 g][64 k] row-major global)
    for (int i = tid; i < 256 * 32; i += 256) {
        int gg = i >> 5, k2 = i & 31;
        float2 w0 = *reinterpret_cast<const float2*>(Whh0g + (size_t)gg * Hh + 2 * k2);
        float2 wa = *reinterpret_cast<const float2*>(Wih1g + (size_t)gg * Hh + 2 * k2);
        float2 wb = *reinterpret_cast<const float2*>(Whh1g + (size_t)gg * Hh + 2 * k2);
        W0[k2 * 256 + gg] = pack2(w0.x, w0.y);
        Wa[k2 * 256 + gg] = pack2(wa.x, wa.y);
        Wb[k2 * 256 + gg] = pack2(wb.x, wb.y);
    }
    // Indices for this CTA's 4 batch rows (dtype-adaptive)
    const int is64 = g_is64;
    for (int i = tid; i < 4 * Ss; i += 256) {
        int r = i >> 9, t = i & (Ss - 1);
        long long v;
        if (is64) v = ((const long long*)seq_raw)[(size_t)(brow0 + r) * Ss + t];
        else      v = (long long)((const int*)seq_raw)[(size_t)(brow0 + r) * Ss + t];
        idxs[r * Ss + t] = (int)v;
    }
    b1s[tid] = bih1[tid] + bhh1[tid];
    h0s[tid] = 0.f;
    h1s[tid] = 0.f;
    float c0 = 0.f, c1 = 0.f;
    __syncthreads();

    const int gg = tid;            // GEMV role: gate column
    const int rr = tid >> 6;       // cell-update role: batch row
    const int jj = tid & 63;       // cell-update role: hidden unit
    const ull* h0p = (const ull*)h0s;  // [4][32] packed pairs
    const ull* h1p = (const ull*)h1s;
    const float* pT = g_projT;

    for (int t = 0; t < Ss; ++t) {
        // Gather layer-0 input projections (L2-resident table) — issued early
        float xv0 = pT[(size_t)idxs[0 * Ss + t] * Gg + gg];
        float xv1 = pT[(size_t)idxs[1 * Ss + t] * Gg + gg];
        float xv2 = pT[(size_t)idxs[2 * Ss + t] * Gg + gg];
        float xv3 = pT[(size_t)idxs[3 * Ss + t] * Gg + gg];

        // ---- layer 0: gates = xp + h0 @ Whh0^T ----
        ull a0 = 0, a1 = 0, a2 = 0, a3 = 0;
#pragma unroll 4
        for (int k2 = 0; k2 < 32; ++k2) {
            ull w = W0[k2 * 256 + gg];
            a0 = ffma2(h0p[0 * 32 + k2], w, a0);
            a1 = ffma2(h0p[1 * 32 + k2], w, a1);
            a2 = ffma2(h0p[2 * 32 + k2], w, a2);
            a3 = ffma2(h0p[3 * 32 + k2], w, a3);
        }
        gts[gg * 5 + 0] = hsum2(a0) + xv0;
        gts[gg * 5 + 1] = hsum2(a1) + xv1;
        gts[gg * 5 + 2] = hsum2(a2) + xv2;
        gts[gg * 5 + 3] = hsum2(a3) + xv3;
        __syncthreads();
        {
            float iv = sigmf(gts[jj * 5 + rr]);
            float fv = sigmf(gts[(64 + jj) * 5 + rr]);
            float gv = tanhf(gts[(128 + jj) * 5 + rr]);
            float ov = sigmf(gts[(192 + jj) * 5 + rr]);
            c0 = fv * c0 + iv * gv;
            h0s[rr * 64 + jj] = ov * tanhf(c0);
        }
        __syncthreads();

        // ---- layer 1: gates = b1 + y0 @ Wih1^T + h1 @ Whh1^T ----
        ull d0 = 0, d1 = 0, d2 = 0, d3 = 0;
#pragma unroll 2
        for (int k2 = 0; k2 < 32; ++k2) {
            ull wa = Wa[k2 * 256 + gg];
            ull wb = Wb[k2 * 256 + gg];
            d0 = ffma2(h0p[0 * 32 + k2], wa, d0);
            d1 = ffma2(h0p[1 * 32 + k2], wa, d1);
            d2 = ffma2(h0p[2 * 32 + k2], wa, d2);
            d3 = ffma2(h0p[3 * 32 + k2], wa, d3);
            d0 = ffma2(h1p[0 * 32 + k2], wb, d0);
            d1 = ffma2(h1p[1 * 32 + k2], wb, d1);
            d2 = ffma2(h1p[2 * 32 + k2], wb, d2);
            d3 = ffma2(h1p[3 * 32 + k2], wb, d3);
        }
        float bb = b1s[gg];
        gts[gg * 5 + 0] = hsum2(d0) + bb;
        gts[gg * 5 + 1] = hsum2(d1) + bb;
        gts[gg * 5 + 2] = hsum2(d2) + bb;
        gts[gg * 5 + 3] = hsum2(d3) + bb;
        __syncthreads();
        {
            float iv = sigmf(gts[jj * 5 + rr]);
            float fv = sigmf(gts[(64 + jj) * 5 + rr]);
            float gv = tanhf(gts[(128 + jj) * 5 + rr]);
            float ov = sigmf(gts[(192 + jj) * 5 + rr]);
            c1 = fv * c1 + iv * gv;
            h1s[rr * 64 + jj] = ov * tanhf(c1);
        }
        __syncthreads();
    }

    // ---- final FC: out = sigmoid(h1_T @ Wfc^T + bfc), shape [B, 2] ----
    if (tid < 8) {
        int r = tid >> 1, o = tid & 1;
        float s = bfc[o];
#pragma unroll
        for (int j = 0; j < 64; ++j) s += h1s[r * 64 + j] * Wfc[o * 64 + j];
        out[(size_t)(brow0 + r) * 2 + o] = sigmf(s);
    }
}

// ---------------------------------------------------------------------------
extern "C" void kernel_launch(void* const* d_in, const int* in_sizes, int n_in,
                              void* d_out, int out_size) {
    const void*  seq  = d_in[0];
    const float* emb  = (const float*)d_in[1];
    const float* Wih0 = (const float*)d_in[2];
    const float* Whh0 = (const float*)d_in[3];
    const float* bih0 = (const float*)d_in[4];
    const float* bhh0 = (const float*)d_in[5];
    const float* Wih1 = (const float*)d_in[6];
    const float* Whh1 = (const float*)d_in[7];
    const float* bih1 = (const float*)d_in[8];
    const float* bhh1 = (const float*)d_in[9];
    const float* Wfc  = (const float*)d_in[10];
    const float* bfc  = (const float*)d_in[11];
    float* out = (float*)d_out;

    const int projSmem = (64 * 256 + 64 * 32) * 8;                       // 147456
    const int lstmSmem = 3 * 32 * 256 * 8 + (512 + 1280 + 256) * 4 + 4 * Ss * 4;  // 212992

    cudaFuncSetAttribute(proj_kernel, cudaFuncAttributeMaxDynamicSharedMemorySize, projSmem);
    cudaFuncSetAttribute(lstm_kernel, cudaFuncAttributeMaxDynamicSharedMemorySize, lstmSmem);

    detect_kernel<<<1, 32>>>((const unsigned int*)seq);
    proj_kernel<<<(Vv + 31) / 32, 256, projSmem>>>(emb, Wih0, bih0, bhh0);
    lstm_kernel<<<Bb / 4, 256, lstmSmem>>>(seq, Whh0, Wih1, Whh1,
                                           bih1, bhh1, Wfc, bfc, out);
}

// round 7
// speedup vs baseline: 1.1346x; 1.1346x over previous
#include <cuda_runtime.h>

// Problem constants
#define Vv 50000
#define Ee 128
#define Hh 64
#define Gg 256   // 4*H
#define Bb 512
#define Ss 512

// 51.2 MB scratch: projTable[v][g] = emb[v] @ Wih0^T + (bih0+bhh0)
__device__ float g_projT[Vv * (size_t)Gg];
__device__ int g_is64;

typedef unsigned long long ull;

__device__ __forceinline__ ull ffma2(ull a, ull b, ull acc) {
    ull d;
    asm("fma.rn.f32x2 %0, %1, %2, %3;" : "=l"(d) : "l"(a), "l"(b), "l"(acc));
    return d;
}
__device__ __forceinline__ ull pack2(float lo, float hi) {
    return ((ull)__float_as_uint(hi) << 32) | (ull)__float_as_uint(lo);
}
__device__ __forceinline__ float hsum2(ull a) {
    return __uint_as_float((unsigned int)a) + __uint_as_float((unsigned int)(a >> 32));
}
__device__ __forceinline__ float sigmf(float x) {
    return __fdividef(1.0f, 1.0f + __expf(-x));
}
__device__ __forceinline__ float tanhfast(float x) {
    // 1 - 2/(e^{2x}+1); saturates correctly at +-1 via MUFU rcp(inf)=0 / exp(-big)=0
    float e = __expf(2.0f * x);
    return 1.0f - __fdividef(2.0f, e + 1.0f);
}

// ---------------------------------------------------------------------------
// Phase A: projTable[V,256] = emb[V,128] @ Wih0^T[128,256] + (bih0+bhh0)
// Also performs int64-vs-int32 sniffing of input_seq (block 0, thread 0).
// ---------------------------------------------------------------------------
__global__ void __launch_bounds__(256, 1)
proj_kernel(const float* __restrict__ emb, const float* __restrict__ Wih0,
            const float* __restrict__ bih0, const float* __restrict__ bhh0,
            const void* __restrict__ seq_raw) {
    extern __shared__ ull sm[];
    ull* Wsm = sm;               // [64 k2][256 g]
    ull* Esm = sm + 64 * 256;    // [64 k2][32 r]

    const int tid = threadIdx.x;
    const int v0 = blockIdx.x * 32;

    if (blockIdx.x == 0 && tid == 0) {
        // int64 little-endian values < 2^31 have all-zero high words
        const unsigned int* wd = (const unsigned int*)seq_raw;
        int is64 = 1;
        for (int i = 0; i < 128; ++i)
            if (wd[2 * i + 1] != 0u) { is64 = 0; break; }
        g_is64 = is64;
    }

    // Load Wih0: global [g][e] row-major -> smem [k2][g] as (e=2k2, 2k2+1) pair
    for (int i = tid; i < 256 * 64; i += 256) {
        int gg = i >> 6, k2 = i & 63;
        float2 w = *reinterpret_cast<const float2*>(Wih0 + (size_t)gg * Ee + 2 * k2);
        Wsm[k2 * 256 + gg] = pack2(w.x, w.y);
    }
    // Load 32 emb rows -> smem [k2][r]
    for (int i = tid; i < 32 * 64; i += 256) {
        int r = i >> 6, k2 = i & 63;
        int v = v0 + r;
        float2 e = make_float2(0.f, 0.f);
        if (v < Vv) e = *reinterpret_cast<const float2*>(emb + (size_t)v * Ee + 2 * k2);
        Esm[k2 * 32 + r] = pack2(e.x, e.y);
    }
    __syncthreads();

    const int gg = tid;  // output column
    ull acc[32];
#pragma unroll
    for (int r = 0; r < 32; ++r) acc[r] = 0ull;

#pragma unroll 2
    for (int k2 = 0; k2 < 64; ++k2) {
        ull w = Wsm[k2 * 256 + gg];
        const ull* ep = &Esm[k2 * 32];
#pragma unroll
        for (int r = 0; r < 32; ++r) acc[r] = ffma2(ep[r], w, acc[r]);
    }

    float b0 = bih0[gg] + bhh0[gg];
#pragma unroll
    for (int r = 0; r < 32; ++r) {
        int v = v0 + r;
        if (v < Vv) g_projT[(size_t)v * Gg + gg] = hsum2(acc[r]) + b0;
    }
}

// ---------------------------------------------------------------------------
// Phase B: fused 2-layer LSTM recurrence + final FC.
// 128 CTAs x 4 batch rows, 256 threads.
//   * permuted gate mapping: warp w, lane l -> g = (l>>3)*64 + 8w + (l&7)
//     so all 4 gates of (row, j) live in one warp -> warp-local exchange.
//   * double-buffered h0/h1 (row stride 72) -> only 2 CTA barriers per step.
//   * all smem accesses are 128-bit (weights repacked [k4][g] ulonglong2).
// ---------------------------------------------------------------------------
__global__ void __launch_bounds__(256, 1)
lstm_kernel(const void* __restrict__ seq_raw,
            const float* __restrict__ Whh0g, const float* __restrict__ Wih1g,
            const float* __restrict__ Whh1g,
            const float* __restrict__ bih1, const float* __restrict__ bhh1,
            const float* __restrict__ Wfc, const float* __restrict__ bfc,
            float* __restrict__ out) {
    extern __shared__ __align__(16) char smraw[];
    ulonglong2* W0v = (ulonglong2*)smraw;   // [16 k4][256 g]
    ulonglong2* Wav = W0v + 16 * 256;
    ulonglong2* Wbv = Wav + 16 * 256;
    float* h0f = (float*)(Wbv + 16 * 256);  // [2 buf][4 r][72]
    float* h1f = h0f + 576;                 // [2 buf][4 r][72]
    float* gts = h1f + 576;                 // [8 warp][8 j][4 q][4 r]
    float* b1s = gts + 1024;                // [256]
    int*   idxs = (int*)(b1s + 256);        // [4 r][512 t]

    const int tid = threadIdx.x;
    const int brow0 = blockIdx.x * 4;

    // Repack the three recurrent matrices ([256 g][64 k] row-major global)
    // into [k4][g] ulonglong2 (two packed f32x2 pairs covering k=4k4..4k4+3).
    for (int i = tid; i < 16 * 256; i += 256) {
        int gg = i >> 4, k4 = i & 15;
        float4 w0 = *(const float4*)(Whh0g + (size_t)gg * Hh + k4 * 4);
        float4 wa = *(const float4*)(Wih1g + (size_t)gg * Hh + k4 * 4);
        float4 wb = *(const float4*)(Whh1g + (size_t)gg * Hh + k4 * 4);
        W0v[k4 * 256 + gg] = make_ulonglong2(pack2(w0.x, w0.y), pack2(w0.z, w0.w));
        Wav[k4 * 256 + gg] = make_ulonglong2(pack2(wa.x, wa.y), pack2(wa.z, wa.w));
        Wbv[k4 * 256 + gg] = make_ulonglong2(pack2(wb.x, wb.y), pack2(wb.z, wb.w));
    }
    // Indices for this CTA's 4 batch rows (dtype-adaptive)
    const int is64 = g_is64;
    for (int i = tid; i < 4 * Ss; i += 256) {
        int r = i >> 9, t = i & (Ss - 1);
        long long v;
        if (is64) v = ((const long long*)seq_raw)[(size_t)(brow0 + r) * Ss + t];
        else      v = (long long)((const int*)seq_raw)[(size_t)(brow0 + r) * Ss + t];
        idxs[r * Ss + t] = (int)v;
    }
    b1s[tid] = bih1[tid] + bhh1[tid];
    for (int i = tid; i < 1152; i += 256) h0f[i] = 0.f;  // zeros h0f+h1f (contiguous)
    __syncthreads();

    const int lane = tid & 31;
    const int w    = tid >> 5;
    const int qq   = lane >> 3;        // gate quarter (i,f,g,o)
    const int jl   = lane & 7;
    const int g    = qq * 64 + w * 8 + jl;   // GEMV gate column
    const int ar   = qq;               // activation role: row = lane>>3
    const int aj   = w * 8 + jl;       // activation role: hidden unit
    float* gw = gts + w * 128;
    const float bb = b1s[g];
    const float* pT = g_projT;
    float c0 = 0.f, c1 = 0.f;

#pragma unroll 1
    for (int t = 0; t < Ss; ++t) {
        const int p = t & 1;
        const ulonglong2* h0rd = (const ulonglong2*)(h0f + p * 288);
        const ulonglong2* h0nw = (const ulonglong2*)(h0f + (p ^ 1) * 288);
        float* h0wr = h0f + (p ^ 1) * 288;
        const ulonglong2* h1rd = (const ulonglong2*)(h1f + p * 288);
        float* h1wr = h1f + (p ^ 1) * 288;

        // Layer-0 input projections from L2-resident table (issued early)
        float xv0 = pT[(size_t)idxs[0 * Ss + t] * Gg + g];
        float xv1 = pT[(size_t)idxs[1 * Ss + t] * Gg + g];
        float xv2 = pT[(size_t)idxs[2 * Ss + t] * Gg + g];
        float xv3 = pT[(size_t)idxs[3 * Ss + t] * Gg + g];

        // ---- layer 0 GEMV: gates = xp + h0 @ Whh0^T ----
        ull a0 = 0, a1 = 0, a2 = 0, a3 = 0, a4 = 0, a5 = 0, a6 = 0, a7 = 0;
#pragma unroll
        for (int k4 = 0; k4 < 16; ++k4) {
            ulonglong2 wv = W0v[k4 * 256 + g];
            ulonglong2 hA = h0rd[k4];
            ulonglong2 hB = h0rd[18 + k4];
            ulonglong2 hC = h0rd[36 + k4];
            ulonglong2 hD = h0rd[54 + k4];
            a0 = ffma2(hA.x, wv.x, a0); a1 = ffma2(hA.y, wv.y, a1);
            a2 = ffma2(hB.x, wv.x, a2); a3 = ffma2(hB.y, wv.y, a3);
            a4 = ffma2(hC.x, wv.x, a4); a5 = ffma2(hC.y, wv.y, a5);
            a6 = ffma2(hD.x, wv.x, a6); a7 = ffma2(hD.y, wv.y, a7);
        }
        {
            float4 v;
            v.x = hsum2(a0) + hsum2(a1) + xv0;
            v.y = hsum2(a2) + hsum2(a3) + xv1;
            v.z = hsum2(a4) + hsum2(a5) + xv2;
            v.w = hsum2(a6) + hsum2(a7) + xv3;
            *(float4*)(gw + jl * 16 + qq * 4) = v;   // conflict-free STS.128
        }
        __syncwarp();
        {
            float gi = gw[jl * 16 + 0  + ar];
            float gf = gw[jl * 16 + 4  + ar];
            float gG = gw[jl * 16 + 8  + ar];
            float go = gw[jl * 16 + 12 + ar];
            float iv = sigmf(gi), fv = sigmf(gf);
            float gv = tanhfast(gG), ov = sigmf(go);
            c0 = fv * c0 + iv * gv;
            h0wr[ar * 72 + aj] = ov * tanhfast(c0);  // conflict-free (stride 72)
        }
        __syncthreads();  // bar 1: h0(new) visible to layer-1 GEMV

        // ---- layer 1 GEMV: gates = b1 + y0 @ Wih1^T + h1 @ Whh1^T ----
        ull d0 = 0, d1 = 0, d2 = 0, d3 = 0, d4 = 0, d5 = 0, d6 = 0, d7 = 0;
#pragma unroll 8
        for (int k4 = 0; k4 < 16; ++k4) {
            ulonglong2 wa = Wav[k4 * 256 + g];
            ulonglong2 wb = Wbv[k4 * 256 + g];
            ulonglong2 yA = h0nw[k4];
            ulonglong2 yB = h0nw[18 + k4];
            ulonglong2 yC = h0nw[36 + k4];
            ulonglong2 yD = h0nw[54 + k4];
            ulonglong2 zA = h1rd[k4];
            ulonglong2 zB = h1rd[18 + k4];
            ulonglong2 zC = h1rd[36 + k4];
            ulonglong2 zD = h1rd[54 + k4];
            d0 = ffma2(yA.x, wa.x, d0); d1 = ffma2(yA.y, wa.y, d1);
            d0 = ffma2(zA.x, wb.x, d0); d1 = ffma2(zA.y, wb.y, d1);
            d2 = ffma2(yB.x, wa.x, d2); d3 = ffma2(yB.y, wa.y, d3);
            d2 = ffma2(zB.x, wb.x, d2); d3 = ffma2(zB.y, wb.y, d3);
            d4 = ffma2(yC.x, wa.x, d4); d5 = ffma2(yC.y, wa.y, d5);
            d4 = ffma2(zC.x, wb.x, d4); d5 = ffma2(zC.y, wb.y, d5);
            d6 = ffma2(yD.x, wa.x, d6); d7 = ffma2(yD.y, wa.y, d7);
            d6 = ffma2(zD.x, wb.x, d6); d7 = ffma2(zD.y, wb.y, d7);
        }
        {
            float4 v;
            v.x = hsum2(d0) + hsum2(d1) + bb;
            v.y = hsum2(d2) + hsum2(d3) + bb;
            v.z = hsum2(d4) + hsum2(d5) + bb;
            v.w = hsum2(d6) + hsum2(d7) + bb;
            *(float4*)(gw + jl * 16 + qq * 4) = v;
        }
        __syncwarp();
        {
            float gi = gw[jl * 16 + 0  + ar];
            float gf = gw[jl * 16 + 4  + ar];
            float gG = gw[jl * 16 + 8  + ar];
            float go = gw[jl * 16 + 12 + ar];
            float iv = sigmf(gi), fv = sigmf(gf);
            float gv = tanhfast(gG), ov = sigmf(go);
            c1 = fv * c1 + iv * gv;
            h1wr[ar * 72 + aj] = ov * tanhfast(c1);
        }
        __syncthreads();  // bar 2: h0/h1(new) safe for next step
    }

    // ---- final FC: out = sigmoid(h1_T @ Wfc^T + bfc), shape [B, 2] ----
    if (tid < 8) {
        const float* hfin = h1f + (((Ss - 1) & 1) ^ 1) * 288;
        int r = tid >> 1, o = tid & 1;
        float s = bfc[o];
#pragma unroll
        for (int j = 0; j < 64; ++j) s += hfin[r * 72 + j] * Wfc[o * 64 + j];
        out[(size_t)(brow0 + r) * 2 + o] = sigmf(s);
    }
}

// ---------------------------------------------------------------------------
extern "C" void kernel_launch(void* const* d_in, const int* in_sizes, int n_in,
                              void* d_out, int out_size) {
    const void*  seq  = d_in[0];
    const float* emb  = (const float*)d_in[1];
    const float* Wih0 = (const float*)d_in[2];
    const float* Whh0 = (const float*)d_in[3];
    const float* bih0 = (const float*)d_in[4];
    const float* bhh0 = (const float*)d_in[5];
    const float* Wih1 = (const float*)d_in[6];
    const float* Whh1 = (const float*)d_in[7];
    const float* bih1 = (const float*)d_in[8];
    const float* bhh1 = (const float*)d_in[9];
    const float* Wfc  = (const float*)d_in[10];
    const float* bfc  = (const float*)d_in[11];
    float* out = (float*)d_out;

    const int projSmem = (64 * 256 + 64 * 32) * 8;                       // 147456
    const int lstmSmem = 3 * 16 * 256 * 16 + (1152 + 1024 + 256) * 4 + 4 * Ss * 4;  // 214528

    cudaFuncSetAttribute(proj_kernel, cudaFuncAttributeMaxDynamicSharedMemorySize, projSmem);
    cudaFuncSetAttribute(lstm_kernel, cudaFuncAttributeMaxDynamicSharedMemorySize, lstmSmem);

    proj_kernel<<<(Vv + 31) / 32, 256, projSmem>>>(emb, Wih0, bih0, bhh0, seq);
    lstm_kernel<<<Bb / 4, 256, lstmSmem>>>(seq, Whh0, Wih1, Whh1,
                                           bih1, bhh1, Wfc, bfc, out);
}

// round 11
// speedup vs baseline: 1.3448x; 1.1853x over previous
#include <cuda_runtime.h>

// Problem constants
#define Vv 50000
#define Ee 128
#define Hh 64
#define Gg 256   // 4*H
#define Bb 512
#define Ss 512

// 51.2 MB scratch: projTable[v][g] = emb[v] @ Wih0^T + (bih0+bhh0)
__device__ float g_projT[Vv * (size_t)Gg];
__device__ int g_is64;

typedef unsigned long long ull;

__device__ __forceinline__ ull ffma2(ull a, ull b, ull acc) {
    ull d;
    asm("fma.rn.f32x2 %0, %1, %2, %3;" : "=l"(d) : "l"(a), "l"(b), "l"(acc));
    return d;
}
__device__ __forceinline__ ull pack2(float lo, float hi) {
    return ((ull)__float_as_uint(hi) << 32) | (ull)__float_as_uint(lo);
}
__device__ __forceinline__ float hsum2(ull a) {
    return __uint_as_float((unsigned int)a) + __uint_as_float((unsigned int)(a >> 32));
}
__device__ __forceinline__ float sigmf(float x) {
    return __fdividef(1.0f, 1.0f + __expf(-x));
}
__device__ __forceinline__ float tanhfast(float x) {
    // 1 - 2/(e^{2x}+1); saturates correctly at +-1 via MUFU rcp(inf)=0 / exp(-big)=0
    float e = __expf(2.0f * x);
    return 1.0f - __fdividef(2.0f, e + 1.0f);
}

// ---------------------------------------------------------------------------
// Phase A: projTable[V,256] = emb[V,128] @ Wih0^T[128,256] + (bih0+bhh0)
// Also performs int64-vs-int32 sniffing of input_seq (block 0, thread 0).
// ---------------------------------------------------------------------------
__global__ void __launch_bounds__(256, 1)
proj_kernel(const float* __restrict__ emb, const float* __restrict__ Wih0,
            const float* __restrict__ bih0, const float* __restrict__ bhh0,
            const void* __restrict__ seq_raw) {
    extern __shared__ ull sm[];
    ull* Wsm = sm;               // [64 k2][256 g]
    ull* Esm = sm + 64 * 256;    // [64 k2][32 r]

    const int tid = threadIdx.x;
    const int v0 = blockIdx.x * 32;

    if (blockIdx.x == 0 && tid == 0) {
        // int64 little-endian values < 2^31 have all-zero high words
        const unsigned int* wd = (const unsigned int*)seq_raw;
        int is64 = 1;
        for (int i = 0; i < 128; ++i)
            if (wd[2 * i + 1] != 0u) { is64 = 0; break; }
        g_is64 = is64;
    }

    // Load Wih0: global [g][e] row-major -> smem [k2][g] as (e=2k2, 2k2+1) pair
    for (int i = tid; i < 256 * 64; i += 256) {
        int gg = i >> 6, k2 = i & 63;
        float2 w = *reinterpret_cast<const float2*>(Wih0 + (size_t)gg * Ee + 2 * k2);
        Wsm[k2 * 256 + gg] = pack2(w.x, w.y);
    }
    // Load 32 emb rows -> smem [k2][r]
    for (int i = tid; i < 32 * 64; i += 256) {
        int r = i >> 6, k2 = i & 63;
        int v = v0 + r;
        float2 e = make_float2(0.f, 0.f);
        if (v < Vv) e = *reinterpret_cast<const float2*>(emb + (size_t)v * Ee + 2 * k2);
        Esm[k2 * 32 + r] = pack2(e.x, e.y);
    }
    __syncthreads();

    const int gg = tid;  // output column
    ull acc[32];
#pragma unroll
    for (int r = 0; r < 32; ++r) acc[r] = 0ull;

#pragma unroll 2
    for (int k2 = 0; k2 < 64; ++k2) {
        ull w = Wsm[k2 * 256 + gg];
        const ull* ep = &Esm[k2 * 32];
#pragma unroll
        for (int r = 0; r < 32; ++r) acc[r] = ffma2(ep[r], w, acc[r]);
    }

    float b0 = bih0[gg] + bhh0[gg];
#pragma unroll
    for (int r = 0; r < 32; ++r) {
        int v = v0 + r;
        if (v < Vv) g_projT[(size_t)v * Gg + gg] = hsum2(acc[r]) + b0;
    }
}

// ---------------------------------------------------------------------------
// Phase B: fused 2-layer LSTM recurrence + final FC.
// 128 CTAs x 4 batch rows, 256 threads.
//   * permuted gate mapping: warp w, lane l -> g = (l>>3)*64 + 8w + (l&7)
//     so all 4 gates of (row, j) live in one warp -> warp-local exchange.
//   * layer-1 weights (Wih1[g,:], Whh1[g,:]) live in REGISTERS (128 regs/thr),
//     loaded once from global. Only Whh0 remains in smem -> crossbar traffic
//     per step drops ~2x (was the 76%-of-peak L1 bottleneck).
//   * double-buffered h0/h1 (row stride 72) -> only 2 CTA barriers per step.
// ---------------------------------------------------------------------------
__global__ void __launch_bounds__(256, 1)
lstm_kernel(const void* __restrict__ seq_raw,
            const float* __restrict__ Whh0g, const float* __restrict__ Wih1g,
            const float* __restrict__ Whh1g,
            const float* __restrict__ bih1, const float* __restrict__ bhh1,
            const float* __restrict__ Wfc, const float* __restrict__ bfc,
            float* __restrict__ out) {
    extern __shared__ __align__(16) char smraw[];
    ulonglong2* W0v = (ulonglong2*)smraw;   // Whh0 [16 k4][256 g]
    float* h0f = (float*)(W0v + 16 * 256);  // [2 buf][4 r][72]
    float* h1f = h0f + 576;                 // [2 buf][4 r][72]
    float* gts = h1f + 576;                 // [8 warp][8 j][4 q][4 r]
    float* b1s = gts + 1024;                // [256]
    int*   idxs = (int*)(b1s + 256);        // [4 r][512 t]

    const int tid = threadIdx.x;
    const int brow0 = blockIdx.x * 4;

    const int lane = tid & 31;
    const int w    = tid >> 5;
    const int qq   = lane >> 3;        // gate quarter (i,f,g,o)
    const int jl   = lane & 7;
    const int g    = qq * 64 + w * 8 + jl;   // GEMV gate column
    const int ar   = qq;               // activation role: row = lane>>3
    const int aj   = w * 8 + jl;       // activation role: hidden unit

    // Repack Whh0 ([256 g][64 k] row-major global) -> smem [k4][g] ulonglong2.
    for (int i = tid; i < 16 * 256; i += 256) {
        int gg = i >> 4, k4 = i & 15;
        float4 w0 = *(const float4*)(Whh0g + (size_t)gg * Hh + k4 * 4);
        W0v[k4 * 256 + gg] = make_ulonglong2(pack2(w0.x, w0.y), pack2(w0.z, w0.w));
    }
    // Layer-1 weights for this thread's gate column -> registers (64 ull).
    ull wa[32], wb[32];
#pragma unroll
    for (int k2 = 0; k2 < 32; ++k2) {
        float2 a = *(const float2*)(Wih1g + (size_t)g * Hh + 2 * k2);
        float2 b = *(const float2*)(Whh1g + (size_t)g * Hh + 2 * k2);
        wa[k2] = pack2(a.x, a.y);
        wb[k2] = pack2(b.x, b.y);
    }
    // Indices for this CTA's 4 batch rows (dtype-adaptive)
    const int is64 = g_is64;
    for (int i = tid; i < 4 * Ss; i += 256) {
        int r = i >> 9, t = i & (Ss - 1);
        long long v;
        if (is64) v = ((const long long*)seq_raw)[(size_t)(brow0 + r) * Ss + t];
        else      v = (long long)((const int*)seq_raw)[(size_t)(brow0 + r) * Ss + t];
        idxs[r * Ss + t] = (int)v;
    }
    b1s[tid] = bih1[tid] + bhh1[tid];
    for (int i = tid; i < 1152; i += 256) h0f[i] = 0.f;  // zeros h0f+h1f (contiguous)
    __syncthreads();

    float* gw = gts + w * 128;
    const float bb = b1s[g];
    const float* pT = g_projT;
    float c0 = 0.f, c1 = 0.f;

#pragma unroll 1
    for (int t = 0; t < Ss; ++t) {
        const int p = t & 1;
        const ulonglong2* h0rd = (const ulonglong2*)(h0f + p * 288);
        const ulonglong2* h0nw = (const ulonglong2*)(h0f + (p ^ 1) * 288);
        float* h0wr = h0f + (p ^ 1) * 288;
        const ulonglong2* h1rd = (const ulonglong2*)(h1f + p * 288);
        float* h1wr = h1f + (p ^ 1) * 288;

        // Layer-0 input projections from L2-resident table (issued early)
        float xv0 = pT[(size_t)idxs[0 * Ss + t] * Gg + g];
        float xv1 = pT[(size_t)idxs[1 * Ss + t] * Gg + g];
        float xv2 = pT[(size_t)idxs[2 * Ss + t] * Gg + g];
        float xv3 = pT[(size_t)idxs[3 * Ss + t] * Gg + g];

        // ---- layer 0 GEMV: gates = xp + h0 @ Whh0^T ----
        ull a0 = 0, a1 = 0, a2 = 0, a3 = 0, a4 = 0, a5 = 0, a6 = 0, a7 = 0;
#pragma unroll
        for (int k4 = 0; k4 < 16; ++k4) {
            ulonglong2 wv = W0v[k4 * 256 + g];
            ulonglong2 hA = h0rd[k4];
            ulonglong2 hB = h0rd[18 + k4];
            ulonglong2 hC = h0rd[36 + k4];
            ulonglong2 hD = h0rd[54 + k4];
            a0 = ffma2(hA.x, wv.x, a0); a1 = ffma2(hA.y, wv.y, a1);
            a2 = ffma2(hB.x, wv.x, a2); a3 = ffma2(hB.y, wv.y, a3);
            a4 = ffma2(hC.x, wv.x, a4); a5 = ffma2(hC.y, wv.y, a5);
            a6 = ffma2(hD.x, wv.x, a6); a7 = ffma2(hD.y, wv.y, a7);
        }
        {
            float4 v;
            v.x = hsum2(a0) + hsum2(a1) + xv0;
            v.y = hsum2(a2) + hsum2(a3) + xv1;
            v.z = hsum2(a4) + hsum2(a5) + xv2;
            v.w = hsum2(a6) + hsum2(a7) + xv3;
            *(float4*)(gw + jl * 16 + qq * 4) = v;   // conflict-free STS.128
        }
        __syncwarp();
        {
            float gi = gw[jl * 16 + 0  + ar];
            float gf = gw[jl * 16 + 4  + ar];
            float gG = gw[jl * 16 + 8  + ar];
            float go = gw[jl * 16 + 12 + ar];
            float iv = sigmf(gi), fv = sigmf(gf);
            float gv = tanhfast(gG), ov = sigmf(go);
            c0 = fv * c0 + iv * gv;
            h0wr[ar * 72 + aj] = ov * tanhfast(c0);  // conflict-free (stride 72)
        }
        __syncthreads();  // bar 1: h0(new) visible to layer-1 GEMV

        // ---- layer 1 GEMV: gates = b1 + y0 @ Wih1^T + h1 @ Whh1^T ----
        // Weights come from registers; only h/y0 broadcast loads hit smem.
        ull d0 = 0, d1 = 0, d2 = 0, d3 = 0, d4 = 0, d5 = 0, d6 = 0, d7 = 0;
#pragma unroll
        for (int k4 = 0; k4 < 16; ++k4) {
            ulonglong2 yA = h0nw[k4];
            ulonglong2 yB = h0nw[18 + k4];
            ulonglong2 yC = h0nw[36 + k4];
            ulonglong2 yD = h0nw[54 + k4];
            ulonglong2 zA = h1rd[k4];
            ulonglong2 zB = h1rd[18 + k4];
            ulonglong2 zC = h1rd[36 + k4];
            ulonglong2 zD = h1rd[54 + k4];
            d0 = ffma2(yA.x, wa[2 * k4], d0); d1 = ffma2(yA.y, wa[2 * k4 + 1], d1);
            d0 = ffma2(zA.x, wb[2 * k4], d0); d1 = ffma2(zA.y, wb[2 * k4 + 1], d1);
            d2 = ffma2(yB.x, wa[2 * k4], d2); d3 = ffma2(yB.y, wa[2 * k4 + 1], d3);
            d2 = ffma2(zB.x, wb[2 * k4], d2); d3 = ffma2(zB.y, wb[2 * k4 + 1], d3);
            d4 = ffma2(yC.x, wa[2 * k4], d4); d5 = ffma2(yC.y, wa[2 * k4 + 1], d5);
            d4 = ffma2(zC.x, wb[2 * k4], d4); d5 = ffma2(zC.y, wb[2 * k4 + 1], d5);
            d6 = ffma2(yD.x, wa[2 * k4], d6); d7 = ffma2(yD.y, wa[2 * k4 + 1], d7);
            d6 = ffma2(zD.x, wb[2 * k4], d6); d7 = ffma2(zD.y, wb[2 * k4 + 1], d7);
        }
        {
            float4 v;
            v.x = hsum2(d0) + hsum2(d1) + bb;
            v.y = hsum2(d2) + hsum2(d3) + bb;
            v.z = hsum2(d4) + hsum2(d5) + bb;
            v.w = hsum2(d6) + hsum2(d7) + bb;
            *(float4*)(gw + jl * 16 + qq * 4) = v;
        }
        __syncwarp();
        {
            float gi = gw[jl * 16 + 0  + ar];
            float gf = gw[jl * 16 + 4  + ar];
            float gG = gw[jl * 16 + 8  + ar];
            float go = gw[jl * 16 + 12 + ar];
            float iv = sigmf(gi), fv = sigmf(gf);
            float gv = tanhfast(gG), ov = sigmf(go);
            c1 = fv * c1 + iv * gv;
            h1wr[ar * 72 + aj] = ov * tanhfast(c1);
        }
        __syncthreads();  // bar 2: h0/h1(new) safe for next step
    }

    // ---- final FC: out = sigmoid(h1_T @ Wfc^T + bfc), shape [B, 2] ----
    if (tid < 8) {
        const float* hfin = h1f + (((Ss - 1) & 1) ^ 1) * 288;
        int r = tid >> 1, o = tid & 1;
        float s = bfc[o];
#pragma unroll
        for (int j = 0; j < 64; ++j) s += hfin[r * 72 + j] * Wfc[o * 64 + j];
        out[(size_t)(brow0 + r) * 2 + o] = sigmf(s);
    }
}

// ---------------------------------------------------------------------------
extern "C" void kernel_launch(void* const* d_in, const int* in_sizes, int n_in,
                              void* d_out, int out_size) {
    const void*  seq  = d_in[0];
    const float* emb  = (const float*)d_in[1];
    const float* Wih0 = (const float*)d_in[2];
    const float* Whh0 = (const float*)d_in[3];
    const float* bih0 = (const float*)d_in[4];
    const float* bhh0 = (const float*)d_in[5];
    const float* Wih1 = (const float*)d_in[6];
    const float* Whh1 = (const float*)d_in[7];
    const float* bih1 = (const float*)d_in[8];
    const float* bhh1 = (const float*)d_in[9];
    const float* Wfc  = (const float*)d_in[10];
    const float* bfc  = (const float*)d_in[11];
    float* out = (float*)d_out;

    const int projSmem = (64 * 256 + 64 * 32) * 8;                         // 147456
    const int lstmSmem = 16 * 256 * 16 + (1152 + 1024 + 256) * 4 + 4 * Ss * 4;  // 83456

    cudaFuncSetAttribute(proj_kernel, cudaFuncAttributeMaxDynamicSharedMemorySize, projSmem);
    cudaFuncSetAttribute(lstm_kernel, cudaFuncAttributeMaxDynamicSharedMemorySize, lstmSmem);

    proj_kernel<<<(Vv + 31) / 32, 256, projSmem>>>(emb, Wih0, bih0, bhh0, seq);
    lstm_kernel<<<Bb / 4, 256, lstmSmem>>>(seq, Whh0, Wih1, Whh1,
                                           bih1, bhh1, Wfc, bfc, out);
}